// round 5
// baseline (speedup 1.0000x reference)
#include <cuda_runtime.h>
#include <math.h>

// ---------------- problem constants ----------------
#define BATCH   2
#define TSEQ    1024
#define DM      1024
#define NHEAD   16
#define HD      64
#define NLAYER  12
#define DFF     2730
#define CAP     128
#define NSLOTS  128
#define TOPK    8
#define NTOK    (BATCH*TSEQ)      // 2048

// ---------------- scratch (device globals; no allocation allowed) ----------------
__device__ float g_x    [NTOK*DM];
__device__ float g_xn   [NTOK*DM];
__device__ float g_qkv  [NTOK*3*DM];
__device__ float g_attn [NTOK*DM];
__device__ float g_ff1  [NTOK*DFF];
__device__ float g_ff2  [NTOK*DFF];
__device__ float g_retr [NTOK*DM];
__device__ float g_retrp[NTOK*DM];
__device__ float g_sim  [NTOK*NSLOTS];
__device__ float g_g1   [NTOK*512];
__device__ float g_h1   [NTOK*2048];
__device__ float g_xs   [BATCH*CAP*DM];
__device__ float g_scores[NTOK];
__device__ int   g_idx  [BATCH*CAP];

// ---------------- helpers ----------------
__device__ __forceinline__ float warpSum(float v){
    #pragma unroll
    for (int o=16;o>0;o>>=1) v += __shfl_xor_sync(0xffffffffu, v, o);
    return v;
}
__device__ __forceinline__ float warpMax(float v){
    #pragma unroll
    for (int o=16;o>0;o>>=1) v = fmaxf(v, __shfl_xor_sync(0xffffffffu, v, o));
    return v;
}
__device__ __forceinline__ float blockSum(float v, float* red){
    int lane = threadIdx.x & 31, w = threadIdx.x >> 5, nw = blockDim.x >> 5;
    v = warpSum(v);
    if (lane == 0) red[w] = v;
    __syncthreads();
    float r = (w == 0 && lane < nw) ? red[lane] : 0.f;
    if (w == 0) r = warpSum(r);
    if (threadIdx.x == 0) red[0] = r;
    __syncthreads();
    float out = red[0];
    __syncthreads();
    return out;
}
__device__ __forceinline__ float blockMax(float v, float* red){
    int lane = threadIdx.x & 31, w = threadIdx.x >> 5, nw = blockDim.x >> 5;
    v = warpMax(v);
    if (lane == 0) red[w] = v;
    __syncthreads();
    float r = (w == 0 && lane < nw) ? red[lane] : -INFINITY;
    if (w == 0) r = warpMax(r);
    if (threadIdx.x == 0) red[0] = r;
    __syncthreads();
    float out = red[0];
    __syncthreads();
    return out;
}
__device__ __forceinline__ float gelu_f(float v){
    return 0.5f * v * (1.f + erff(v * 0.70710678118654752f));
}
__device__ __forceinline__ float silu_f(float v){
    return v / (1.f + expf(-v));
}

// ---------------- SGEMM: C[M,N] = epilogue(A[M,K] @ B[N,K]^T) ----------------
// EP: 0 store, 1 C=res+acc, 2 C=gelu(acc), 3 C=res+acc+bias[n], 4 C=silu(res)*acc
#define EP_STORE    0
#define EP_ADD      1
#define EP_GELU     2
#define EP_ADD_BIAS 3
#define EP_SILU_MUL 4

template<int EP>
__global__ __launch_bounds__(256, 2)
void sgemm_abt(float* __restrict__ C, const float* __restrict__ A,
               const float* __restrict__ B, int M, int N, int K,
               int lda, int ldb, int ldc,
               const float* __restrict__ res, int ldres,
               const float* __restrict__ bias)
{
    __shared__ float As[8][132];
    __shared__ float Bs[8][132];
    const int bm = blockIdx.y * 128, bn = blockIdx.x * 128;
    const int tid = threadIdx.x;
    const int tx = tid & 15, ty = tid >> 4;

    float acc[8][8];
    #pragma unroll
    for (int i = 0; i < 8; i++)
        #pragma unroll
        for (int j = 0; j < 8; j++) acc[i][j] = 0.f;

    for (int k0 = 0; k0 < K; k0 += 8) {
        #pragma unroll
        for (int i = 0; i < 4; i++) {
            int e  = tid + i * 256;
            int kk = e & 7, mm = e >> 3;
            int gk = k0 + kk;
            int gm = bm + mm;
            As[kk][mm] = (gm < M && gk < K) ? A[(size_t)gm * lda + gk] : 0.f;
            int gn = bn + mm;
            Bs[kk][mm] = (gn < N && gk < K) ? B[(size_t)gn * ldb + gk] : 0.f;
        }
        __syncthreads();
        #pragma unroll
        for (int kk = 0; kk < 8; kk++) {
            float4 a0 = *(const float4*)&As[kk][ty * 8];
            float4 a1 = *(const float4*)&As[kk][ty * 8 + 4];
            float4 b0 = *(const float4*)&Bs[kk][tx * 8];
            float4 b1 = *(const float4*)&Bs[kk][tx * 8 + 4];
            float a[8] = {a0.x,a0.y,a0.z,a0.w,a1.x,a1.y,a1.z,a1.w};
            float b[8] = {b0.x,b0.y,b0.z,b0.w,b1.x,b1.y,b1.z,b1.w};
            #pragma unroll
            for (int i = 0; i < 8; i++)
                #pragma unroll
                for (int j = 0; j < 8; j++)
                    acc[i][j] = fmaf(a[i], b[j], acc[i][j]);
        }
        __syncthreads();
    }

    #pragma unroll
    for (int i = 0; i < 8; i++) {
        int gm = bm + ty * 8 + i;
        if (gm >= M) continue;
        #pragma unroll
        for (int j = 0; j < 8; j++) {
            int gn = bn + tx * 8 + j;
            if (gn >= N) continue;
            float v = acc[i][j];
            if (EP == EP_ADD)      v += res[(size_t)gm * ldres + gn];
            else if (EP == EP_GELU)     v = gelu_f(v);
            else if (EP == EP_ADD_BIAS) v += res[(size_t)gm * ldres + gn] + bias[gn];
            else if (EP == EP_SILU_MUL) v *= silu_f(res[(size_t)gm * ldres + gn]);
            C[(size_t)gm * ldc + gn] = v;
        }
    }
}

// ---------------- embed + positional ----------------
__global__ void embed_kernel(float* __restrict__ x, const int* __restrict__ ids,
                             const float* __restrict__ emb, const float* __restrict__ pos)
{
    int row = blockIdx.x;          // b*T + t
    int t   = row & (TSEQ - 1);
    int id  = ids[row];
    int tid = threadIdx.x;
    #pragma unroll
    for (int i = 0; i < 4; i++) {
        int d = tid + i * 256;
        x[(size_t)row * DM + d] = emb[(size_t)id * DM + d] + pos[(size_t)t * DM + d];
    }
}

// ---------------- rmsnorm ----------------
__global__ void rms_kernel(float* __restrict__ y, const float* __restrict__ x,
                           const float* __restrict__ w)
{
    __shared__ float red[8];
    int row = blockIdx.x, tid = threadIdx.x;
    const float* xr = x + (size_t)row * DM;
    float s = 0.f;
    #pragma unroll
    for (int i = 0; i < 4; i++) { float v = xr[tid + i * 256]; s = fmaf(v, v, s); }
    s = blockSum(s, red);
    float r = rsqrtf(s * (1.f / DM) + 1e-6f);
    #pragma unroll
    for (int i = 0; i < 4; i++) {
        int d = tid + i * 256;
        y[(size_t)row * DM + d] = xr[d] * r * w[d];
    }
}

// ---------------- attention: one block per (query t, head h, batch b) ----------------
__global__ void attn_kernel(const float* __restrict__ qkv, float* __restrict__ out, int S)
{
    const int t = blockIdx.x, h = blockIdx.y, b = blockIdx.z;
    const int tid = threadIdx.x;   // 128 threads
    __shared__ float qsh[HD];
    __shared__ float sc[TSEQ];
    __shared__ float red[8];
    __shared__ float obuf[HD];
    const float* base = qkv + (size_t)b * S * (3 * DM);
    if (tid < HD) qsh[tid] = base[(size_t)t * (3 * DM) + h * HD + tid];
    __syncthreads();

    float lmax = -INFINITY;
    for (int j = tid; j <= t; j += 128) {
        const float* kr = base + (size_t)j * (3 * DM) + DM + h * HD;
        float s = 0.f;
        #pragma unroll
        for (int d = 0; d < HD; d++) s = fmaf(qsh[d], kr[d], s);
        s *= 0.125f;                 // 1/sqrt(64)
        sc[j] = s;
        lmax = fmaxf(lmax, s);
    }
    float m = blockMax(lmax, red);
    float lsum = 0.f;
    for (int j = tid; j <= t; j += 128) {
        float p = expf(sc[j] - m);
        sc[j] = p;
        lsum += p;
    }
    float ssum = blockSum(lsum, red);
    float inv = 1.f / ssum;

    const int d = tid & 63, half = tid >> 6;
    const float* vb = base + 2 * DM + h * HD + d;
    float o = 0.f;
    for (int j = half; j <= t; j += 2)
        o = fmaf(sc[j], vb[(size_t)j * (3 * DM)], o);
    if (half == 1) obuf[d] = o;
    __syncthreads();
    if (half == 0)
        out[((size_t)(b * S + t)) * DM + h * HD + d] = (o + obuf[d]) * inv;
}

// ---------------- MoD: router scores ----------------
__global__ void score_kernel(float* __restrict__ scores, const float* __restrict__ x,
                             const float* __restrict__ r)
{
    __shared__ float red[8];
    int row = blockIdx.x, tid = threadIdx.x;
    const float* xr = x + (size_t)row * DM;
    float s = 0.f;
    #pragma unroll
    for (int i = 0; i < 4; i++) { int d = tid + i * 256; s = fmaf(xr[d], r[d], s); }
    s = blockSum(s, red);
    if (tid == 0) scores[row] = s;
}

// ---------------- MoD: exact top-128 in descending order (bitonic sort, tie = smaller idx) ----------------
__global__ void topk_sort_kernel(int* __restrict__ idx, const float* __restrict__ scores)
{
    int b = blockIdx.x, tid = threadIdx.x;     // 1024 threads
    __shared__ float s[TSEQ];
    __shared__ int   si[TSEQ];
    s[tid]  = scores[b * TSEQ + tid];
    si[tid] = tid;
    __syncthreads();
    for (int k = 2; k <= TSEQ; k <<= 1) {
        for (int j = k >> 1; j > 0; j >>= 1) {
            int ixj = tid ^ j;
            if (ixj > tid) {
                bool desc = ((tid & k) == 0);
                float s1 = s[tid], s2 = s[ixj];
                int   i1 = si[tid], i2 = si[ixj];
                bool firstBetter = (s1 > s2) || (s1 == s2 && i1 < i2);
                if (desc != firstBetter) {
                    s[tid] = s2; s[ixj] = s1;
                    si[tid] = i2; si[ixj] = i1;
                }
            }
            __syncthreads();
        }
    }
    if (tid < CAP) idx[b * CAP + tid] = si[tid];
}

__global__ void gather_kernel(float* __restrict__ xs, const float* __restrict__ x,
                              const int* __restrict__ idx)
{
    int row = blockIdx.x;            // b*CAP + j
    int b = row >> 7;
    int src = b * TSEQ + idx[row];
    int tid = threadIdx.x;
    #pragma unroll
    for (int i = 0; i < 4; i++) {
        int d = tid + i * 256;
        xs[(size_t)row * DM + d] = x[(size_t)src * DM + d];
    }
}
__global__ void scatter_kernel(float* __restrict__ x, const float* __restrict__ xs,
                               const int* __restrict__ idx)
{
    int row = blockIdx.x;
    int b = row >> 7;
    int dst = b * TSEQ + idx[row];
    int tid = threadIdx.x;
    #pragma unroll
    for (int i = 0; i < 4; i++) {
        int d = tid + i * 256;
        x[(size_t)dst * DM + d] = xs[(size_t)row * DM + d];
    }
}

// ---------------- memory: top-8 + softmax + weighted value gather ----------------
__global__ void memtopk_kernel(float* __restrict__ outp, const float* __restrict__ sim,
                               const float* __restrict__ mem_values)
{
    int row = blockIdx.x, tid = threadIdx.x;   // 128 threads
    __shared__ float sv[NSLOTS];
    __shared__ float av[NSLOTS];
    __shared__ int   ai[NSLOTS];
    __shared__ float wk[TOPK];
    __shared__ int   ik[TOPK];
    sv[tid] = sim[(size_t)row * NSLOTS + tid] * 0.03125f;   // / sqrt(1024)
    __syncthreads();
    for (int k = 0; k < TOPK; k++) {
        av[tid] = sv[tid]; ai[tid] = tid;
        __syncthreads();
        for (int s = 64; s > 0; s >>= 1) {
            if (tid < s) {
                float v2 = av[tid + s]; int i2 = ai[tid + s];
                if (v2 > av[tid] || (v2 == av[tid] && i2 < ai[tid])) { av[tid] = v2; ai[tid] = i2; }
            }
            __syncthreads();
        }
        if (tid == 0) { wk[k] = av[0]; ik[k] = ai[0]; sv[ai[0]] = -INFINITY; }
        __syncthreads();
    }
    if (tid == 0) {
        float mx = wk[0], ssum = 0.f, e[TOPK];
        #pragma unroll
        for (int k = 0; k < TOPK; k++) { e[k] = expf(wk[k] - mx); ssum += e[k]; }
        #pragma unroll
        for (int k = 0; k < TOPK; k++) wk[k] = e[k] / ssum;
    }
    __syncthreads();
    #pragma unroll
    for (int i = 0; i < 8; i++) {
        int d = tid + i * 128;
        float o = 0.f;
        #pragma unroll
        for (int k = 0; k < TOPK; k++)
            o = fmaf(wk[k], mem_values[(size_t)ik[k] * DM + d], o);
        outp[(size_t)row * DM + d] = o;
    }
}

// ---------------- gate: gelu(g1)@w2 + b2 -> sigmoid -> x += gate*retr ----------------
__global__ void gate_kernel(float* __restrict__ x, const float* __restrict__ g1,
                            const float* __restrict__ gw2, const float* __restrict__ gb2,
                            const float* __restrict__ retr)
{
    __shared__ float red[8];
    int row = blockIdx.x, tid = threadIdx.x;   // 256
    float s = 0.f;
    for (int j = tid; j < 512; j += 256) {
        float v = g1[(size_t)row * 512 + j];
        s = fmaf(gelu_f(v), gw2[j], s);
    }
    s = blockSum(s, red);
    float gate = 1.f / (1.f + expf(-(s + gb2[0])));
    #pragma unroll
    for (int i = 0; i < 4; i++) {
        int d = tid + i * 256;
        size_t p = (size_t)row * DM + d;
        x[p] += gate * retr[p];
    }
}

// ---------------- host-side gemm dispatch ----------------
static void gemm(int ep, float* C, const float* A, const float* B,
                 int M, int N, int K, int lda, int ldb, int ldc,
                 const float* res = nullptr, int ldres = 0,
                 const float* bias = nullptr)
{
    dim3 grid((N + 127) / 128, (M + 127) / 128);
    switch (ep) {
    case EP_STORE:    sgemm_abt<EP_STORE>   <<<grid,256>>>(C,A,B,M,N,K,lda,ldb,ldc,res,ldres,bias); break;
    case EP_ADD:      sgemm_abt<EP_ADD>     <<<grid,256>>>(C,A,B,M,N,K,lda,ldb,ldc,res,ldres,bias); break;
    case EP_GELU:     sgemm_abt<EP_GELU>    <<<grid,256>>>(C,A,B,M,N,K,lda,ldb,ldc,res,ldres,bias); break;
    case EP_ADD_BIAS: sgemm_abt<EP_ADD_BIAS><<<grid,256>>>(C,A,B,M,N,K,lda,ldb,ldc,res,ldres,bias); break;
    case EP_SILU_MUL: sgemm_abt<EP_SILU_MUL><<<grid,256>>>(C,A,B,M,N,K,lda,ldb,ldc,res,ldres,bias); break;
    }
}

extern "C" void kernel_launch(void* const* d_in, const int* in_sizes, int n_in,
                              void* d_out, int out_size)
{
    const int*   ids       = (const int*)  d_in[0];
    const float* embed     = (const float*)d_in[1];
    const float* pos       = (const float*)d_in[2];
    const float* n1        = (const float*)d_in[3];
    const float* qkvw      = (const float*)d_in[4];
    const float* outw      = (const float*)d_in[5];
    const float* n2        = (const float*)d_in[6];
    const float* w1        = (const float*)d_in[7];
    const float* w2        = (const float*)d_in[8];
    const float* w3        = (const float*)d_in[9];
    const float* router    = (const float*)d_in[10];
    const float* mem_keys  = (const float*)d_in[11];
    const float* mem_vals  = (const float*)d_in[12];
    const float* mem_q     = (const float*)d_in[13];
    const float* mem_out   = (const float*)d_in[14];
    const float* gate_w1   = (const float*)d_in[15];
    const float* gate_b1   = (const float*)d_in[16];
    const float* gate_w2   = (const float*)d_in[17];
    const float* gate_b2   = (const float*)d_in[18];
    const float* lat_norm  = (const float*)d_in[19];
    const float* lat_w1    = (const float*)d_in[20];
    const float* lat_w2    = (const float*)d_in[21];
    const float* fin_norm  = (const float*)d_in[22];
    const float* lm_head   = (const float*)d_in[23];
    float* out = (float*)d_out;

    float *x,*xn,*qkvb,*attnb,*ff1,*ff2,*retr,*retrp,*sim,*g1,*h1,*xs,*scores;
    int *idxb;
    cudaGetSymbolAddress((void**)&x,     g_x);
    cudaGetSymbolAddress((void**)&xn,    g_xn);
    cudaGetSymbolAddress((void**)&qkvb,  g_qkv);
    cudaGetSymbolAddress((void**)&attnb, g_attn);
    cudaGetSymbolAddress((void**)&ff1,   g_ff1);
    cudaGetSymbolAddress((void**)&ff2,   g_ff2);
    cudaGetSymbolAddress((void**)&retr,  g_retr);
    cudaGetSymbolAddress((void**)&retrp, g_retrp);
    cudaGetSymbolAddress((void**)&sim,   g_sim);
    cudaGetSymbolAddress((void**)&g1,    g_g1);
    cudaGetSymbolAddress((void**)&h1,    g_h1);
    cudaGetSymbolAddress((void**)&xs,    g_xs);
    cudaGetSymbolAddress((void**)&scores,g_scores);
    cudaGetSymbolAddress((void**)&idxb,  g_idx);

    // x = embed[ids] + pos
    embed_kernel<<<NTOK, 256>>>(x, ids, embed, pos);

    // transformer block applied to a contiguous buffer of M rows (S tokens per batch)
    auto run_block = [&](float* buf, int M, int S, int l) {
        const float* Wqkv = qkvw + (size_t)l * 3 * DM * DM;
        const float* Wout = outw + (size_t)l * DM * DM;
        const float* W1   = w1   + (size_t)l * DFF * DM;
        const float* W2   = w2   + (size_t)l * DFF * DM;
        const float* W3   = w3   + (size_t)l * DM * DFF;
        rms_kernel<<<M, 256>>>(xn, buf, n1 + (size_t)l * DM);
        gemm(EP_STORE, qkvb, xn, Wqkv, M, 3 * DM, DM, DM, DM, 3 * DM);
        attn_kernel<<<dim3(S, NHEAD, BATCH), 128>>>(qkvb, attnb, S);
        gemm(EP_ADD, buf, attnb, Wout, M, DM, DM, DM, DM, DM, buf, DM);
        rms_kernel<<<M, 256>>>(xn, buf, n2 + (size_t)l * DM);
        gemm(EP_STORE,    ff1, xn, W1, M, DFF, DM, DM, DM, DFF);
        gemm(EP_SILU_MUL, ff2, xn, W2, M, DFF, DM, DM, DM, DFF, ff1, DFF);
        gemm(EP_ADD,      buf, ff2, W3, M, DM, DFF, DFF, DFF, DM, buf, DM);
    };

    for (int l = 0; l < NLAYER; l++) {
        if (l & 1) {
            // Mixture-of-Depths: route top-CAP tokens (descending score order)
            score_kernel<<<NTOK, 256>>>(scores, x, router + (size_t)l * DM);
            topk_sort_kernel<<<BATCH, TSEQ>>>(idxb, scores);
            gather_kernel<<<BATCH * CAP, 256>>>(xs, x, idxb);
            run_block(xs, BATCH * CAP, CAP, l);
            scatter_kernel<<<BATCH * CAP, 256>>>(x, xs, idxb);
        } else {
            run_block(x, NTOK, TSEQ, l);
        }
    }

    // kNN memory retrieval
    gemm(EP_STORE, xn,  x,  mem_q,    NTOK, DM,     DM, DM, DM, DM);      // q = x @ mem_q^T
    gemm(EP_STORE, sim, xn, mem_keys, NTOK, NSLOTS, DM, DM, DM, NSLOTS);  // sim (unscaled)
    memtopk_kernel<<<NTOK, 128>>>(retrp, sim, mem_vals);
    gemm(EP_STORE, retr, retrp, mem_out, NTOK, DM, DM, DM, DM, DM);
    // gate MLP: g1 = x@W1a^T + retr@W1b^T + b1   (gate_w1 is [512, 2048])
    gemm(EP_STORE,    g1, x,    gate_w1,        NTOK, 512, DM, DM, 2 * DM, 512);
    gemm(EP_ADD_BIAS, g1, retr, gate_w1 + DM,   NTOK, 512, DM, DM, 2 * DM, 512, g1, 512, gate_b1);
    gate_kernel<<<NTOK, 256>>>(x, g1, gate_w2, gate_b2, retr);

    // latent reasoning iterations
    for (int it = 0; it < 4; it++) {
        rms_kernel<<<NTOK, 256>>>(xn, x, lat_norm);
        gemm(EP_GELU, h1, xn, lat_w1, NTOK, 2 * DM, DM, DM, DM, 2 * DM);
        gemm(EP_ADD,  x,  h1, lat_w2, NTOK, DM, 2 * DM, 2 * DM, 2 * DM, DM, x, DM);
    }

    // final norm + LM head
    rms_kernel<<<NTOK, 256>>>(xn, x, fin_norm);
    gemm(EP_STORE, out, xn, lm_head, NTOK, 50257, DM, DM, DM, 50257);
}

// round 7
// speedup vs baseline: 1.1160x; 1.1160x over previous
#include <cuda_runtime.h>
#include <math.h>

// ---------------- problem constants ----------------
#define BATCH   2
#define TSEQ    1024
#define DM      1024
#define NHEAD   16
#define HD      64
#define NLAYER  12
#define DFF     2730
#define CAP     128
#define NSLOTS  128
#define TOPK    8
#define NTOK    (BATCH*TSEQ)      // 2048

// ---------------- scratch (device globals; no allocation allowed) ----------------
__device__ float g_x    [NTOK*DM];
__device__ float g_xn   [NTOK*DM];
__device__ float g_qkv  [NTOK*3*DM];
__device__ float g_attn [NTOK*DM];
__device__ float g_ff1  [NTOK*DFF];
__device__ float g_ff2  [NTOK*DFF];
__device__ float g_retr [NTOK*DM];
__device__ float g_retrp[NTOK*DM];
__device__ float g_sim  [NTOK*NSLOTS];
__device__ float g_g1   [NTOK*512];
__device__ float g_h1   [NTOK*2048];
__device__ float g_xs   [BATCH*CAP*DM];
__device__ float g_scores[NTOK];
__device__ int   g_idx  [BATCH*CAP];

// ---------------- helpers ----------------
__device__ __forceinline__ float warpSum(float v){
    #pragma unroll
    for (int o=16;o>0;o>>=1) v += __shfl_xor_sync(0xffffffffu, v, o);
    return v;
}
__device__ __forceinline__ float warpMax(float v){
    #pragma unroll
    for (int o=16;o>0;o>>=1) v = fmaxf(v, __shfl_xor_sync(0xffffffffu, v, o));
    return v;
}
__device__ __forceinline__ float blockSum(float v, float* red){
    int lane = threadIdx.x & 31, w = threadIdx.x >> 5, nw = blockDim.x >> 5;
    v = warpSum(v);
    if (lane == 0) red[w] = v;
    __syncthreads();
    float r = (w == 0 && lane < nw) ? red[lane] : 0.f;
    if (w == 0) r = warpSum(r);
    if (threadIdx.x == 0) red[0] = r;
    __syncthreads();
    float out = red[0];
    __syncthreads();
    return out;
}
__device__ __forceinline__ float blockMax(float v, float* red){
    int lane = threadIdx.x & 31, w = threadIdx.x >> 5, nw = blockDim.x >> 5;
    v = warpMax(v);
    if (lane == 0) red[w] = v;
    __syncthreads();
    float r = (w == 0 && lane < nw) ? red[lane] : -INFINITY;
    if (w == 0) r = warpMax(r);
    if (threadIdx.x == 0) red[0] = r;
    __syncthreads();
    float out = red[0];
    __syncthreads();
    return out;
}
__device__ __forceinline__ float gelu_f(float v){
    return 0.5f * v * (1.f + erff(v * 0.70710678118654752f));
}
__device__ __forceinline__ float silu_f(float v){
    return v / (1.f + expf(-v));
}

// ---------------- tf32 split + mma ----------------
__device__ __forceinline__ void split_tf32(float v, unsigned &hi, unsigned &lo){
    unsigned h;
    asm("cvt.rna.tf32.f32 %0, %1;" : "=r"(h) : "f"(v));
    float lf = v - __uint_as_float(h);
    unsigned l;
    asm("cvt.rna.tf32.f32 %0, %1;" : "=r"(l) : "f"(lf));
    hi = h; lo = l;
}
__device__ __forceinline__ void mma8(float* c, const unsigned* a, const unsigned* b){
    asm volatile(
        "mma.sync.aligned.m16n8k8.row.col.f32.tf32.tf32.f32 "
        "{%0,%1,%2,%3}, {%4,%5,%6,%7}, {%8,%9}, {%0,%1,%2,%3};"
        : "+f"(c[0]), "+f"(c[1]), "+f"(c[2]), "+f"(c[3])
        : "r"(a[0]), "r"(a[1]), "r"(a[2]), "r"(a[3]), "r"(b[0]), "r"(b[1]));
}

// ---------------- tensor-core GEMM: C[M,N] = epilogue(A[M,K] @ B[N,K]^T) ----------------
// 3xTF32: fp32-equivalent accuracy via hi/lo decomposition.
// EP: 0 store, 1 C=res+acc, 2 C=gelu(acc), 3 C=res+acc+bias[n], 4 C=silu(res)*acc
#define EP_STORE    0
#define EP_ADD      1
#define EP_GELU     2
#define EP_ADD_BIAS 3
#define EP_SILU_MUL 4

template<int EP>
__global__ __launch_bounds__(256)
void tgemm_abt(float* __restrict__ C, const float* __restrict__ A,
               const float* __restrict__ B, int M, int N, int K,
               int lda, int ldb, int ldc,
               const float* __restrict__ res, int ldres,
               const float* __restrict__ bias)
{
    // smem stride 136: 136 % 32 == 8 -> fragment LDS conflict-free
    __shared__ float As[16][136];
    __shared__ float Bs[16][136];
    const int bm = blockIdx.y * 128, bn = blockIdx.x * 128;
    const int tid  = threadIdx.x;
    const int warp = tid >> 5, lane = tid & 31;
    const int wm = (warp & 1) * 64;      // 2 warps along M
    const int wn = (warp >> 1) * 32;     // 4 warps along N
    const int g  = lane >> 2, tg = lane & 3;
    // float4 is only legal when the row stride keeps 16B alignment (lda%4==0).
    const bool a4 = ((lda & 3) == 0);
    const bool b4 = ((ldb & 3) == 0);

    float acc[4][4][4];
    #pragma unroll
    for (int mi = 0; mi < 4; mi++)
        #pragma unroll
        for (int ni = 0; ni < 4; ni++)
            #pragma unroll
            for (int cc = 0; cc < 4; cc++) acc[mi][ni][cc] = 0.f;

    for (int k0 = 0; k0 < K; k0 += 16) {
        // global -> smem (128 rows x 16 k per matrix, 4 floats along K per thread)
        #pragma unroll
        for (int i = 0; i < 2; i++) {
            int e = tid + i * 256;             // 0..511
            int row = e >> 2, vq = e & 3;
            int gk = k0 + vq * 4;
            float4 av = make_float4(0.f, 0.f, 0.f, 0.f);
            int gm = bm + row;
            if (gm < M) {
                const float* ap = A + (size_t)gm * lda + gk;
                if (a4 && gk + 3 < K) av = *(const float4*)ap;
                else {
                    if (gk + 0 < K) av.x = ap[0];
                    if (gk + 1 < K) av.y = ap[1];
                    if (gk + 2 < K) av.z = ap[2];
                    if (gk + 3 < K) av.w = ap[3];
                }
            }
            As[vq * 4 + 0][row] = av.x;
            As[vq * 4 + 1][row] = av.y;
            As[vq * 4 + 2][row] = av.z;
            As[vq * 4 + 3][row] = av.w;

            float4 bv = make_float4(0.f, 0.f, 0.f, 0.f);
            int gn = bn + row;
            if (gn < N) {
                const float* bp = B + (size_t)gn * ldb + gk;
                if (b4 && gk + 3 < K) bv = *(const float4*)bp;
                else {
                    if (gk + 0 < K) bv.x = bp[0];
                    if (gk + 1 < K) bv.y = bp[1];
                    if (gk + 2 < K) bv.z = bp[2];
                    if (gk + 3 < K) bv.w = bp[3];
                }
            }
            Bs[vq * 4 + 0][row] = bv.x;
            Bs[vq * 4 + 1][row] = bv.y;
            Bs[vq * 4 + 2][row] = bv.z;
            Bs[vq * 4 + 3][row] = bv.w;
        }
        __syncthreads();

        #pragma unroll
        for (int ks = 0; ks < 16; ks += 8) {
            unsigned bhi[4][2], blo[4][2];
            #pragma unroll
            for (int ni = 0; ni < 4; ni++) {
                int col = wn + ni * 8 + g;
                split_tf32(Bs[ks + tg][col],     bhi[ni][0], blo[ni][0]);
                split_tf32(Bs[ks + tg + 4][col], bhi[ni][1], blo[ni][1]);
            }
            unsigned ahi[4][4], alo[4][4];
            #pragma unroll
            for (int mi = 0; mi < 4; mi++) {
                int r = wm + mi * 16 + g;
                split_tf32(As[ks + tg][r],         ahi[mi][0], alo[mi][0]);
                split_tf32(As[ks + tg][r + 8],     ahi[mi][1], alo[mi][1]);
                split_tf32(As[ks + tg + 4][r],     ahi[mi][2], alo[mi][2]);
                split_tf32(As[ks + tg + 4][r + 8], ahi[mi][3], alo[mi][3]);
            }
            #pragma unroll
            for (int mi = 0; mi < 4; mi++)
                #pragma unroll
                for (int ni = 0; ni < 4; ni++) {
                    mma8(acc[mi][ni], ahi[mi], bhi[ni]);
                    mma8(acc[mi][ni], ahi[mi], blo[ni]);
                    mma8(acc[mi][ni], alo[mi], bhi[ni]);
                }
        }
        __syncthreads();
    }

    // epilogue
    #pragma unroll
    for (int mi = 0; mi < 4; mi++) {
        int row0 = bm + wm + mi * 16 + g;
        #pragma unroll
        for (int ni = 0; ni < 4; ni++) {
            int col0 = bn + wn + ni * 8 + tg * 2;
            #pragma unroll
            for (int cc = 0; cc < 4; cc++) {
                int gm = row0 + (cc >> 1) * 8;
                int gn = col0 + (cc & 1);
                if (gm < M && gn < N) {
                    float v = acc[mi][ni][cc];
                    if (EP == EP_ADD)           v += res[(size_t)gm * ldres + gn];
                    else if (EP == EP_GELU)     v = gelu_f(v);
                    else if (EP == EP_ADD_BIAS) v += res[(size_t)gm * ldres + gn] + bias[gn];
                    else if (EP == EP_SILU_MUL) v *= silu_f(res[(size_t)gm * ldres + gn]);
                    C[(size_t)gm * ldc + gn] = v;
                }
            }
        }
    }
}

// ---------------- embed + positional ----------------
__global__ void embed_kernel(float* __restrict__ x, const int* __restrict__ ids,
                             const float* __restrict__ emb, const float* __restrict__ pos)
{
    int row = blockIdx.x;          // b*T + t
    int t   = row & (TSEQ - 1);
    int id  = ids[row];
    int tid = threadIdx.x;
    #pragma unroll
    for (int i = 0; i < 4; i++) {
        int d = tid + i * 256;
        x[(size_t)row * DM + d] = emb[(size_t)id * DM + d] + pos[(size_t)t * DM + d];
    }
}

// ---------------- rmsnorm ----------------
__global__ void rms_kernel(float* __restrict__ y, const float* __restrict__ x,
                           const float* __restrict__ w)
{
    __shared__ float red[8];
    int row = blockIdx.x, tid = threadIdx.x;
    const float* xr = x + (size_t)row * DM;
    float s = 0.f;
    #pragma unroll
    for (int i = 0; i < 4; i++) { float v = xr[tid + i * 256]; s = fmaf(v, v, s); }
    s = blockSum(s, red);
    float r = rsqrtf(s * (1.f / DM) + 1e-6f);
    #pragma unroll
    for (int i = 0; i < 4; i++) {
        int d = tid + i * 256;
        y[(size_t)row * DM + d] = xr[d] * r * w[d];
    }
}

// ---------------- attention: one block per (query t, head h, batch b) ----------------
__global__ void attn_kernel(const float* __restrict__ qkv, float* __restrict__ out, int S)
{
    const int t = blockIdx.x, h = blockIdx.y, b = blockIdx.z;
    const int tid = threadIdx.x;   // 128 threads
    __shared__ float qsh[HD];
    __shared__ float sc[TSEQ];
    __shared__ float red[8];
    __shared__ float obuf[HD];
    const float* base = qkv + (size_t)b * S * (3 * DM);
    if (tid < HD) qsh[tid] = base[(size_t)t * (3 * DM) + h * HD + tid];
    __syncthreads();

    float lmax = -INFINITY;
    for (int j = tid; j <= t; j += 128) {
        const float* kr = base + (size_t)j * (3 * DM) + DM + h * HD;
        float s = 0.f;
        #pragma unroll
        for (int d = 0; d < HD; d++) s = fmaf(qsh[d], kr[d], s);
        s *= 0.125f;                 // 1/sqrt(64)
        sc[j] = s;
        lmax = fmaxf(lmax, s);
    }
    float m = blockMax(lmax, red);
    float lsum = 0.f;
    for (int j = tid; j <= t; j += 128) {
        float p = expf(sc[j] - m);
        sc[j] = p;
        lsum += p;
    }
    float ssum = blockSum(lsum, red);
    float inv = 1.f / ssum;

    const int d = tid & 63, half = tid >> 6;
    const float* vb = base + 2 * DM + h * HD + d;
    float o = 0.f;
    for (int j = half; j <= t; j += 2)
        o = fmaf(sc[j], vb[(size_t)j * (3 * DM)], o);
    if (half == 1) obuf[d] = o;
    __syncthreads();
    if (half == 0)
        out[((size_t)(b * S + t)) * DM + h * HD + d] = (o + obuf[d]) * inv;
}

// ---------------- MoD: router scores ----------------
__global__ void score_kernel(float* __restrict__ scores, const float* __restrict__ x,
                             const float* __restrict__ r)
{
    __shared__ float red[8];
    int row = blockIdx.x, tid = threadIdx.x;
    const float* xr = x + (size_t)row * DM;
    float s = 0.f;
    #pragma unroll
    for (int i = 0; i < 4; i++) { int d = tid + i * 256; s = fmaf(xr[d], r[d], s); }
    s = blockSum(s, red);
    if (tid == 0) scores[row] = s;
}

// ---------------- MoD: exact top-128 descending (bitonic sort, tie = smaller idx) ----------------
__global__ void topk_sort_kernel(int* __restrict__ idx, const float* __restrict__ scores)
{
    int b = blockIdx.x, tid = threadIdx.x;     // 1024 threads
    __shared__ float s[TSEQ];
    __shared__ int   si[TSEQ];
    s[tid]  = scores[b * TSEQ + tid];
    si[tid] = tid;
    __syncthreads();
    for (int k = 2; k <= TSEQ; k <<= 1) {
        for (int j = k >> 1; j > 0; j >>= 1) {
            int ixj = tid ^ j;
            if (ixj > tid) {
                bool desc = ((tid & k) == 0);
                float s1 = s[tid], s2 = s[ixj];
                int   i1 = si[tid], i2 = si[ixj];
                bool firstBetter = (s1 > s2) || (s1 == s2 && i1 < i2);
                if (desc != firstBetter) {
                    s[tid] = s2; s[ixj] = s1;
                    si[tid] = i2; si[ixj] = i1;
                }
            }
            __syncthreads();
        }
    }
    if (tid < CAP) idx[b * CAP + tid] = si[tid];
}

__global__ void gather_kernel(float* __restrict__ xs, const float* __restrict__ x,
                              const int* __restrict__ idx)
{
    int row = blockIdx.x;            // b*CAP + j
    int b = row >> 7;
    int src = b * TSEQ + idx[row];
    int tid = threadIdx.x;
    #pragma unroll
    for (int i = 0; i < 4; i++) {
        int d = tid + i * 256;
        xs[(size_t)row * DM + d] = x[(size_t)src * DM + d];
    }
}
__global__ void scatter_kernel(float* __restrict__ x, const float* __restrict__ xs,
                               const int* __restrict__ idx)
{
    int row = blockIdx.x;
    int b = row >> 7;
    int dst = b * TSEQ + idx[row];
    int tid = threadIdx.x;
    #pragma unroll
    for (int i = 0; i < 4; i++) {
        int d = tid + i * 256;
        x[(size_t)dst * DM + d] = xs[(size_t)row * DM + d];
    }
}

// ---------------- memory: top-8 + softmax + weighted value gather ----------------
__global__ void memtopk_kernel(float* __restrict__ outp, const float* __restrict__ sim,
                               const float* __restrict__ mem_values)
{
    int row = blockIdx.x, tid = threadIdx.x;   // 128 threads
    __shared__ float sv[NSLOTS];
    __shared__ float av[NSLOTS];
    __shared__ int   ai[NSLOTS];
    __shared__ float wk[TOPK];
    __shared__ int   ik[TOPK];
    sv[tid] = sim[(size_t)row * NSLOTS + tid] * 0.03125f;   // / sqrt(1024)
    __syncthreads();
    for (int k = 0; k < TOPK; k++) {
        av[tid] = sv[tid]; ai[tid] = tid;
        __syncthreads();
        for (int s = 64; s > 0; s >>= 1) {
            if (tid < s) {
                float v2 = av[tid + s]; int i2 = ai[tid + s];
                if (v2 > av[tid] || (v2 == av[tid] && i2 < ai[tid])) { av[tid] = v2; ai[tid] = i2; }
            }
            __syncthreads();
        }
        if (tid == 0) { wk[k] = av[0]; ik[k] = ai[0]; sv[ai[0]] = -INFINITY; }
        __syncthreads();
    }
    if (tid == 0) {
        float mx = wk[0], ssum = 0.f, e[TOPK];
        #pragma unroll
        for (int k = 0; k < TOPK; k++) { e[k] = expf(wk[k] - mx); ssum += e[k]; }
        #pragma unroll
        for (int k = 0; k < TOPK; k++) wk[k] = e[k] / ssum;
    }
    __syncthreads();
    #pragma unroll
    for (int i = 0; i < 8; i++) {
        int d = tid + i * 128;
        float o = 0.f;
        #pragma unroll
        for (int k = 0; k < TOPK; k++)
            o = fmaf(wk[k], mem_values[(size_t)ik[k] * DM + d], o);
        outp[(size_t)row * DM + d] = o;
    }
}

// ---------------- gate: gelu(g1)@w2 + b2 -> sigmoid -> x += gate*retr ----------------
__global__ void gate_kernel(float* __restrict__ x, const float* __restrict__ g1,
                            const float* __restrict__ gw2, const float* __restrict__ gb2,
                            const float* __restrict__ retr)
{
    __shared__ float red[8];
    int row = blockIdx.x, tid = threadIdx.x;   // 256
    float s = 0.f;
    for (int j = tid; j < 512; j += 256) {
        float v = g1[(size_t)row * 512 + j];
        s = fmaf(gelu_f(v), gw2[j], s);
    }
    s = blockSum(s, red);
    float gate = 1.f / (1.f + expf(-(s + gb2[0])));
    #pragma unroll
    for (int i = 0; i < 4; i++) {
        int d = tid + i * 256;
        size_t p = (size_t)row * DM + d;
        x[p] += gate * retr[p];
    }
}

// ---------------- host-side gemm dispatch ----------------
static void gemm(int ep, float* C, const float* A, const float* B,
                 int M, int N, int K, int lda, int ldb, int ldc,
                 const float* res = nullptr, int ldres = 0,
                 const float* bias = nullptr)
{
    dim3 grid((N + 127) / 128, (M + 127) / 128);
    switch (ep) {
    case EP_STORE:    tgemm_abt<EP_STORE>   <<<grid,256>>>(C,A,B,M,N,K,lda,ldb,ldc,res,ldres,bias); break;
    case EP_ADD:      tgemm_abt<EP_ADD>     <<<grid,256>>>(C,A,B,M,N,K,lda,ldb,ldc,res,ldres,bias); break;
    case EP_GELU:     tgemm_abt<EP_GELU>    <<<grid,256>>>(C,A,B,M,N,K,lda,ldb,ldc,res,ldres,bias); break;
    case EP_ADD_BIAS: tgemm_abt<EP_ADD_BIAS><<<grid,256>>>(C,A,B,M,N,K,lda,ldb,ldc,res,ldres,bias); break;
    case EP_SILU_MUL: tgemm_abt<EP_SILU_MUL><<<grid,256>>>(C,A,B,M,N,K,lda,ldb,ldc,res,ldres,bias); break;
    }
}

extern "C" void kernel_launch(void* const* d_in, const int* in_sizes, int n_in,
                              void* d_out, int out_size)
{
    const int*   ids       = (const int*)  d_in[0];
    const float* embed     = (const float*)d_in[1];
    const float* pos       = (const float*)d_in[2];
    const float* n1        = (const float*)d_in[3];
    const float* qkvw      = (const float*)d_in[4];
    const float* outw      = (const float*)d_in[5];
    const float* n2        = (const float*)d_in[6];
    const float* w1        = (const float*)d_in[7];
    const float* w2        = (const float*)d_in[8];
    const float* w3        = (const float*)d_in[9];
    const float* router    = (const float*)d_in[10];
    const float* mem_keys  = (const float*)d_in[11];
    const float* mem_vals  = (const float*)d_in[12];
    const float* mem_q     = (const float*)d_in[13];
    const float* mem_out   = (const float*)d_in[14];
    const float* gate_w1   = (const float*)d_in[15];
    const float* gate_b1   = (const float*)d_in[16];
    const float* gate_w2   = (const float*)d_in[17];
    const float* gate_b2   = (const float*)d_in[18];
    const float* lat_norm  = (const float*)d_in[19];
    const float* lat_w1    = (const float*)d_in[20];
    const float* lat_w2    = (const float*)d_in[21];
    const float* fin_norm  = (const float*)d_in[22];
    const float* lm_head   = (const float*)d_in[23];
    float* out = (float*)d_out;

    float *x,*xn,*qkvb,*attnb,*ff1,*ff2,*retr,*retrp,*sim,*g1,*h1,*xs,*scores;
    int *idxb;
    cudaGetSymbolAddress((void**)&x,     g_x);
    cudaGetSymbolAddress((void**)&xn,    g_xn);
    cudaGetSymbolAddress((void**)&qkvb,  g_qkv);
    cudaGetSymbolAddress((void**)&attnb, g_attn);
    cudaGetSymbolAddress((void**)&ff1,   g_ff1);
    cudaGetSymbolAddress((void**)&ff2,   g_ff2);
    cudaGetSymbolAddress((void**)&retr,  g_retr);
    cudaGetSymbolAddress((void**)&retrp, g_retrp);
    cudaGetSymbolAddress((void**)&sim,   g_sim);
    cudaGetSymbolAddress((void**)&g1,    g_g1);
    cudaGetSymbolAddress((void**)&h1,    g_h1);
    cudaGetSymbolAddress((void**)&xs,    g_xs);
    cudaGetSymbolAddress((void**)&scores,g_scores);
    cudaGetSymbolAddress((void**)&idxb,  g_idx);

    // x = embed[ids] + pos
    embed_kernel<<<NTOK, 256>>>(x, ids, embed, pos);

    // transformer block applied to a contiguous buffer of M rows (S tokens per batch)
    auto run_block = [&](float* buf, int M, int S, int l) {
        const float* Wqkv = qkvw + (size_t)l * 3 * DM * DM;
        const float* Wout = outw + (size_t)l * DM * DM;
        const float* W1   = w1   + (size_t)l * DFF * DM;
        const float* W2   = w2   + (size_t)l * DFF * DM;
        const float* W3   = w3   + (size_t)l * DM * DFF;
        rms_kernel<<<M, 256>>>(xn, buf, n1 + (size_t)l * DM);
        gemm(EP_STORE, qkvb, xn, Wqkv, M, 3 * DM, DM, DM, DM, 3 * DM);
        attn_kernel<<<dim3(S, NHEAD, BATCH), 128>>>(qkvb, attnb, S);
        gemm(EP_ADD, buf, attnb, Wout, M, DM, DM, DM, DM, DM, buf, DM);
        rms_kernel<<<M, 256>>>(xn, buf, n2 + (size_t)l * DM);
        gemm(EP_STORE,    ff1, xn, W1, M, DFF, DM, DM, DM, DFF);
        gemm(EP_SILU_MUL, ff2, xn, W2, M, DFF, DM, DM, DM, DFF, ff1, DFF);
        gemm(EP_ADD,      buf, ff2, W3, M, DM, DFF, DFF, DFF, DM, buf, DM);
    };

    for (int l = 0; l < NLAYER; l++) {
        if (l & 1) {
            // Mixture-of-Depths: route top-CAP tokens (descending score order)
            score_kernel<<<NTOK, 256>>>(scores, x, router + (size_t)l * DM);
            topk_sort_kernel<<<BATCH, TSEQ>>>(idxb, scores);
            gather_kernel<<<BATCH * CAP, 256>>>(xs, x, idxb);
            run_block(xs, BATCH * CAP, CAP, l);
            scatter_kernel<<<BATCH * CAP, 256>>>(x, xs, idxb);
        } else {
            run_block(x, NTOK, TSEQ, l);
        }
    }

    // kNN memory retrieval
    gemm(EP_STORE, xn,  x,  mem_q,    NTOK, DM,     DM, DM, DM, DM);      // q = x @ mem_q^T
    gemm(EP_STORE, sim, xn, mem_keys, NTOK, NSLOTS, DM, DM, DM, NSLOTS);  // sim (unscaled)
    memtopk_kernel<<<NTOK, 128>>>(retrp, sim, mem_vals);
    gemm(EP_STORE, retr, retrp, mem_out, NTOK, DM, DM, DM, DM, DM);
    // gate MLP: g1 = x@W1a^T + retr@W1b^T + b1   (gate_w1 is [512, 2048])
    gemm(EP_STORE,    g1, x,    gate_w1,        NTOK, 512, DM, DM, 2 * DM, 512);
    gemm(EP_ADD_BIAS, g1, retr, gate_w1 + DM,   NTOK, 512, DM, DM, 2 * DM, 512, g1, 512, gate_b1);
    gate_kernel<<<NTOK, 256>>>(x, g1, gate_w2, gate_b2, retr);

    // latent reasoning iterations
    for (int it = 0; it < 4; it++) {
        rms_kernel<<<NTOK, 256>>>(xn, x, lat_norm);
        gemm(EP_GELU, h1, xn, lat_w1, NTOK, 2 * DM, DM, DM, DM, 2 * DM);
        gemm(EP_ADD,  x,  h1, lat_w2, NTOK, DM, 2 * DM, 2 * DM, 2 * DM, DM, x, DM);
    }

    // final norm + LM head
    rms_kernel<<<NTOK, 256>>>(xn, x, fin_norm);
    gemm(EP_STORE, out, xn, lm_head, NTOK, 50257, DM, DM, DM, 50257);
}